// round 3
// baseline (speedup 1.0000x reference)
#include <cuda_runtime.h>
#include <cuda_fp16.h>

#define B_  4
#define Q_  512
#define KK_ 1024
#define D_  512
#define H_  128
#define DV_ 512

// Scratch (device globals; no allocation allowed in kernel_launch)
__device__ float g_qp[B_ * Q_ * H_];      // 1 MB
__device__ float g_kp[B_ * KK_ * H_];     // 2 MB
__device__ float g_attn[B_ * Q_ * KK_];   // 8 MB

__device__ __forceinline__ __half2 tanh_h2(__half2 x) {
    unsigned xi = *(unsigned*)&x, yi;
    asm("tanh.approx.f16x2 %0, %1;" : "=r"(yi) : "r"(xi));
    return *(__half2*)&yi;
}

// ---- packed f32x2 helpers (sm_103a: FFMA2 reachable only via PTX) ----
__device__ __forceinline__ unsigned long long bcast2(float a) {
    unsigned long long r;
    asm("mov.b64 %0, {%1, %1};" : "=l"(r) : "f"(a));
    return r;
}
__device__ __forceinline__ void fma2(unsigned long long& d,
                                     unsigned long long a, unsigned long long b) {
    asm("fma.rn.f32x2 %0, %1, %2, %3;" : "=l"(d) : "l"(a), "l"(b), "l"(d));
}
__device__ __forceinline__ float2 unpack2(unsigned long long v) {
    float2 f;
    asm("mov.b64 {%0, %1}, %2;" : "=f"(f.x), "=f"(f.y) : "l"(v));
    return f;
}

// ---- cp.async helpers ----
__device__ __forceinline__ void cp_async16(void* smem, const void* gmem) {
    unsigned saddr = (unsigned)__cvta_generic_to_shared(smem);
    asm volatile("cp.async.cg.shared.global [%0], [%1], 16;\n" :: "r"(saddr), "l"(gmem));
}
__device__ __forceinline__ void cp_commit() {
    asm volatile("cp.async.commit_group;\n");
}
template<int N> __device__ __forceinline__ void cp_wait() {
    asm volatile("cp.async.wait_group %0;\n" :: "n"(N));
}

// ----------------------------------------------------------------------------
// Kernel 1: projections. C[row, h] = sum_d A[row, d] * W[d, h]
// BM=32, BN=64 (H split in halves), BK=32, 128 threads, micro 4x4.
// Grid 384: blk<128 -> qp (64 row-tiles x 2 col-halves), else kp (128 x 2).
// ----------------------------------------------------------------------------
__global__ __launch_bounds__(128) void proj_kernel(
    const float* __restrict__ Aq, const float* __restrict__ Ak,
    const float* __restrict__ Wq, const float* __restrict__ Wk)
{
    __shared__ float As[2][32 * 32];
    __shared__ float Ws[2][32 * 64];

    int blk = blockIdx.x;
    const float* A;
    const float* W;
    float* C;
    int rowbase, nb;
    if (blk < 128) { A = Aq; W = Wq; C = g_qp; rowbase = (blk >> 1) * 32; nb = (blk & 1) * 64; }
    else {
        int t = blk - 128;
        A = Ak; W = Wk; C = g_kp; rowbase = (t >> 1) * 32; nb = (t & 1) * 64;
    }

    int tid = threadIdx.x;
    int tx = tid & 15;            // col group: nb + tx*4
    int ty = tid >> 4;            // row group: ty*4 .. +3

    unsigned long long acc[4][2];
#pragma unroll
    for (int i = 0; i < 4; i++) { acc[i][0] = 0ull; acc[i][1] = 0ull; }

#define PROJ_STAGE(kk, buf)                                                     \
    do {                                                                        \
        _Pragma("unroll")                                                       \
        for (int i_ = 0; i_ < 2; i_++) {                                        \
            int idx_ = tid + i_ * 128;                                          \
            int r_ = idx_ >> 3, c_ = (idx_ & 7) << 2;                           \
            cp_async16(&As[buf][r_ * 32 + c_],                                  \
                       A + (size_t)(rowbase + r_) * D_ + (kk) + c_);            \
        }                                                                       \
        _Pragma("unroll")                                                       \
        for (int i_ = 0; i_ < 4; i_++) {                                        \
            int idx_ = tid + i_ * 128;                                          \
            int r_ = idx_ >> 4, c_ = (idx_ & 15) << 2;                          \
            cp_async16(&Ws[buf][r_ * 64 + c_],                                  \
                       W + (size_t)((kk) + r_) * H_ + nb + c_);                 \
        }                                                                       \
        cp_commit();                                                            \
    } while (0)

    PROJ_STAGE(0, 0);
    for (int s = 0; s < 16; s++) {
        int buf = s & 1;
        if (s + 1 < 16) { PROJ_STAGE((s + 1) * 32, (s + 1) & 1); cp_wait<1>(); }
        else            { cp_wait<0>(); }
        __syncthreads();
#pragma unroll
        for (int k = 0; k < 32; k++) {
            const ulonglong2 bv = *(const ulonglong2*)&Ws[buf][k * 64 + tx * 4];
#pragma unroll
            for (int i = 0; i < 4; i++) {
                unsigned long long pa = bcast2(As[buf][(ty * 4 + i) * 32 + k]);
                fma2(acc[i][0], pa, bv.x);
                fma2(acc[i][1], pa, bv.y);
            }
        }
        __syncthreads();
    }
#undef PROJ_STAGE

#pragma unroll
    for (int i = 0; i < 4; i++) {
        float2 lo = unpack2(acc[i][0]);
        float2 hi = unpack2(acc[i][1]);
        float4 v = make_float4(lo.x, lo.y, hi.x, hi.y);
        *(float4*)(C + (size_t)(rowbase + ty * 4 + i) * H_ + nb + tx * 4) = v;
    }
}

// ----------------------------------------------------------------------------
// Kernel 2: scores + softmax. Block: 128 threads = 4 warps, warp w owns q-row.
// Grid = B*Q/4 = 512. Scores kept in registers (32 per lane). kp chunks (32
// rows, padded stride 132) double-buffered via cp.async.
// tanh evaluated as tanh.approx.f16x2 (2 evals per MUFU issue).
// ----------------------------------------------------------------------------
__global__ __launch_bounds__(128) void score_softmax_kernel(const float* __restrict__ wv_g)
{
    __shared__ float kp_sm[2][32 * 132];
    __shared__ float q_sm[4 * 128];
    __shared__ float w_sm[128];

    int tid = threadIdx.x;
    int w = tid >> 5;
    int l = tid & 31;

    int qb = blockIdx.x * 4;
    int b  = qb >> 9;
    int q0 = qb & 511;

    {
        int r = tid >> 5, c = (tid & 31) << 2;
        *(float4*)&q_sm[r * 128 + c] =
            *(const float4*)&g_qp[(size_t)(b * Q_ + q0 + r) * H_ + c];
        if (tid < 32) *(float4*)&w_sm[tid * 4] = *(const float4*)&wv_g[tid * 4];
    }

    const float* kp_base = g_kp + (size_t)b * KK_ * H_;

#define KP_STAGE(ch, buf)                                                       \
    do {                                                                        \
        _Pragma("unroll")                                                       \
        for (int i_ = 0; i_ < 8; i_++) {                                        \
            int idx_ = tid + i_ * 128;                                          \
            int r_ = idx_ >> 5, c_ = (idx_ & 31) << 2;                          \
            cp_async16(&kp_sm[buf][r_ * 132 + c_],                              \
                       &kp_base[(size_t)((ch) * 32 + r_) * H_ + c_]);           \
        }                                                                       \
        cp_commit();                                                            \
    } while (0)

    float s[32];

    KP_STAGE(0, 0);
    for (int ch = 0; ch < 32; ch++) {
        int buf = ch & 1;
        if (ch + 1 < 32) { KP_STAGE(ch + 1, (ch + 1) & 1); cp_wait<1>(); }
        else             { cp_wait<0>(); }
        __syncthreads();

        const float4* kr = (const float4*)&kp_sm[buf][l * 132];
        const float4* qr = (const float4*)&q_sm[w * 128];
        const float4* wr = (const float4*)w_sm;
        float s0 = 0.f, s1 = 0.f, s2 = 0.f, s3 = 0.f;
#pragma unroll
        for (int h = 0; h < 32; h++) {
            float4 kv = kr[h];
            float4 qv = qr[h];
            float4 wv = wr[h];
            float2 t01 = __half22float2(tanh_h2(__floats2half2_rn(qv.x + kv.x, qv.y + kv.y)));
            float2 t23 = __half22float2(tanh_h2(__floats2half2_rn(qv.z + kv.z, qv.w + kv.w)));
            s0 += wv.x * t01.x;
            s1 += wv.y * t01.y;
            s2 += wv.z * t23.x;
            s3 += wv.w * t23.y;
        }
        s[ch] = (s0 + s1) + (s2 + s3);
        __syncthreads();
    }
#undef KP_STAGE

    // softmax: lane l holds scores for k = ch*32 + l
    float m = -1e30f;
#pragma unroll
    for (int j = 0; j < 32; j++) m = fmaxf(m, s[j]);
#pragma unroll
    for (int o = 16; o; o >>= 1) m = fmaxf(m, __shfl_xor_sync(0xffffffffu, m, o));
    float sum = 0.f;
#pragma unroll
    for (int j = 0; j < 32; j++) { s[j] = __expf(s[j] - m); sum += s[j]; }
#pragma unroll
    for (int o = 16; o; o >>= 1) sum += __shfl_xor_sync(0xffffffffu, sum, o);
    float inv = 1.0f / sum;

    float* arow = g_attn + (size_t)(b * Q_ + q0 + w) * KK_;
#pragma unroll
    for (int j = 0; j < 32; j++) arow[j * 32 + l] = s[j] * inv;
}

// ----------------------------------------------------------------------------
// Kernel 3: out[b] = attn[b] @ values[b].  M=512, N=512, Kd=1024 per batch.
// BM=64, BN=128, BK=16, 256 threads, micro 4x8 (4 f32x2 pairs), double-buffer.
// Grid (4, 8, 4) = 128 blocks = one wave.
// ----------------------------------------------------------------------------
__global__ __launch_bounds__(256) void av_gemm_kernel(
    const float* __restrict__ values, float* __restrict__ out)
{
    __shared__ float As[2][64 * 16];
    __shared__ float Bs[2][16 * 128];

    int b  = blockIdx.z;
    int mb = blockIdx.y * 64;
    int nb = blockIdx.x * 128;

    const float* Ab = g_attn + (size_t)b * Q_ * KK_;     // [512,1024]
    const float* Bb = values + (size_t)b * KK_ * DV_;    // [1024,512]
    float* Ob = out + (size_t)b * Q_ * DV_;

    int tid = threadIdx.x;
    int tx = tid & 15;     // cols nb + tx*8 .. +7
    int ty = tid >> 4;     // rows mb + ty*4 .. +3

    unsigned long long acc[4][4];
#pragma unroll
    for (int i = 0; i < 4; i++)
#pragma unroll
        for (int j = 0; j < 4; j++) acc[i][j] = 0ull;

#define AV_STAGE(kk, buf)                                                       \
    do {                                                                        \
        {                                                                       \
            int r_ = tid >> 2, c_ = (tid & 3) << 2;                             \
            cp_async16(&As[buf][r_ * 16 + c_],                                  \
                       Ab + (size_t)(mb + r_) * KK_ + (kk) + c_);               \
        }                                                                       \
        _Pragma("unroll")                                                       \
        for (int i_ = 0; i_ < 2; i_++) {                                        \
            int idx_ = tid + i_ * 256;                                          \
            int r_ = idx_ >> 5, c_ = (idx_ & 31) << 2;                          \
            cp_async16(&Bs[buf][r_ * 128 + c_],                                 \
                       Bb + (size_t)((kk) + r_) * DV_ + nb + c_);               \
        }                                                                       \
        cp_commit();                                                            \
    } while (0)

    AV_STAGE(0, 0);
    for (int s = 0; s < 64; s++) {
        int buf = s & 1;
        if (s + 1 < 64) { AV_STAGE((s + 1) * 16, (s + 1) & 1); cp_wait<1>(); }
        else            { cp_wait<0>(); }
        __syncthreads();
#pragma unroll
        for (int k = 0; k < 16; k++) {
            const ulonglong2 bv0 = *(const ulonglong2*)&Bs[buf][k * 128 + tx * 8];
            const ulonglong2 bv1 = *(const ulonglong2*)&Bs[buf][k * 128 + tx * 8 + 4];
#pragma unroll
            for (int i = 0; i < 4; i++) {
                unsigned long long pa = bcast2(As[buf][(ty * 4 + i) * 16 + k]);
                fma2(acc[i][0], pa, bv0.x);
                fma2(acc[i][1], pa, bv0.y);
                fma2(acc[i][2], pa, bv1.x);
                fma2(acc[i][3], pa, bv1.y);
            }
        }
        __syncthreads();
    }
#undef AV_STAGE

#pragma unroll
    for (int i = 0; i < 4; i++) {
        float2 p0 = unpack2(acc[i][0]);
        float2 p1 = unpack2(acc[i][1]);
        float2 p2 = unpack2(acc[i][2]);
        float2 p3 = unpack2(acc[i][3]);
        float* orow = Ob + (size_t)(mb + ty * 4 + i) * DV_ + nb + tx * 8;
        *(float4*)(orow)     = make_float4(p0.x, p0.y, p1.x, p1.y);
        *(float4*)(orow + 4) = make_float4(p2.x, p2.y, p3.x, p3.y);
    }
}

// ----------------------------------------------------------------------------
extern "C" void kernel_launch(void* const* d_in, const int* in_sizes, int n_in,
                              void* d_out, int out_size)
{
    const float* queries = (const float*)d_in[0];  // [4,512,512]
    const float* keys    = (const float*)d_in[1];  // [4,1024,512]
    const float* values  = (const float*)d_in[2];  // [4,1024,512]
    const float* W_q     = (const float*)d_in[3];  // [512,128]
    const float* W_k     = (const float*)d_in[4];  // [512,128]
    const float* w_v     = (const float*)d_in[5];  // [128]
    float* out = (float*)d_out;                    // [4,512,512]

    proj_kernel<<<384, 128>>>(queries, keys, W_q, W_k);
    score_softmax_kernel<<<512, 128>>>(w_v);
    dim3 g3(4, 8, 4);
    av_gemm_kernel<<<g3, 256>>>(values, out);
}